// round 7
// baseline (speedup 1.0000x reference)
#include <cuda_runtime.h>
#include <cuda_bf16.h>
#include <math.h>
#include <string.h>

#define NROWS   65536
#define DIM     64
#define KC      512
#define NQ      (NROWS*DIM)
#define GRID    148
#define THREADS 256
#define WARPS   8
#define WTILES  (NROWS/32)       // 2048 warp-tiles of 32 rows
#define WSTRIDE (GRID*WARPS)     // 1184
#define DELTA   5e-3f
#define SLOTS   16

// smem byte offsets
#define SMO_SB    0                      // 512 f32 exact code norms
#define SMO_CODES 2048                   // 512 x 36 u32, fragment-interleaved
#define SMO_XBF   (SMO_CODES + 73728)    // 75776: 8 warps x 32 rows x 36 u32
#define SMO_CNT   (SMO_XBF + 36864)      // 112640: 8x32 int
#define SMO_LIST  (SMO_CNT + 1024)       // 113664: 8x32x16 int
#define SMEM_TOTAL (SMO_LIST + 16384)    // 130048

// Output: [0] loss | [1..NQ] quantized_st (base out+1) | [1+NQ] perplexity | [2+NQ..] indices

__device__ unsigned     g_codes[KC*36];
__device__ float        g_sb[KC];
__device__ int          g_hist[KC];
__device__ double       g_sse;
__device__ unsigned int g_done;

__device__ __forceinline__ unsigned pack_bf2(float lo, float hi) {
    __nv_bfloat162 p = __floats2bfloat162_rn(lo, hi);
    unsigned u; memcpy(&u, &p, 4);
    return u;
}

// fragment-interleave remap: pos ks*8+2t+j  <-  orig word ks*8+t+4j
__device__ __forceinline__ int frag_remap(int p) {
    int ks = p >> 3, r = p & 7, t = r >> 1, j = r & 1;
    return ks * 8 + t + 4 * j;
}

// ---- prep: interleaved bf16 code image, exact norms, zero globals -----------
__global__ void prep_kernel(const float* __restrict__ emb) {
    int k = blockIdx.x * blockDim.x + threadIdx.x;
    if (k >= KC) return;
    if (k == 0) { g_sse = 0.0; g_done = 0u; }
    g_hist[k] = 0;

    const float* e = emb + k * DIM;
    float b0 = 0.f, b1 = 0.f;
    #pragma unroll
    for (int i = 0; i < DIM; i += 2) {
        b0 = fmaf(e[i],     e[i],     b0);
        b1 = fmaf(e[i + 1], e[i + 1], b1);
    }
    g_sb[k] = b0 + b1;

    unsigned w[32];
    #pragma unroll
    for (int i = 0; i < 32; i++) w[i] = pack_bf2(e[2 * i], e[2 * i + 1]);
    #pragma unroll
    for (int p = 0; p < 32; p++) g_codes[k * 36 + p] = w[frag_remap(p)];
    #pragma unroll
    for (int p = 32; p < 36; p++) g_codes[k * 36 + p] = 0u;
}

__device__ __forceinline__ void mma_bf16(float* d, unsigned a0, unsigned a1,
                                         unsigned a2, unsigned a3,
                                         unsigned b0, unsigned b1) {
    asm volatile(
        "mma.sync.aligned.m16n8k16.row.col.f32.bf16.bf16.f32 "
        "{%0,%1,%2,%3}, {%4,%5,%6,%7}, {%8,%9}, {%0,%1,%2,%3};"
        : "+f"(d[0]), "+f"(d[1]), "+f"(d[2]), "+f"(d[3])
        : "r"(a0), "r"(a1), "r"(a2), "r"(a3), "r"(b0), "r"(b1));
}

// -----------------------------------------------------------------------------
__global__ void __launch_bounds__(THREADS, 1)
vq_mma_kernel(const float* __restrict__ inp,
              const float* __restrict__ emb,
              float* __restrict__ out)
{
    extern __shared__ char sm[];
    float*    sb    = reinterpret_cast<float*>(sm + SMO_SB);
    unsigned* codes = reinterpret_cast<unsigned*>(sm + SMO_CODES);
    unsigned* xbf   = reinterpret_cast<unsigned*>(sm + SMO_XBF);
    int*      cnt   = reinterpret_cast<int*>(sm + SMO_CNT);
    int*      list  = reinterpret_cast<int*>(sm + SMO_LIST);

    const int tid  = threadIdx.x;
    const int wid  = tid >> 5, lane = tid & 31;
    const int g    = lane >> 2, tg = lane & 3;

    for (int i = tid; i < KC * 36 / 4; i += THREADS)
        reinterpret_cast<uint4*>(codes)[i] =
            reinterpret_cast<const uint4*>(g_codes)[i];
    for (int i = tid; i < KC; i += THREADS) sb[i] = g_sb[i];
    __syncthreads();

    unsigned* xw  = xbf + wid * 32 * 36;
    int*      wcn = cnt + wid * 32;
    int*      wls = list + wid * 32 * SLOTS;

    for (int wt = blockIdx.x * WARPS + wid; wt < WTILES; wt += WSTRIDE) {
        const int row = wt * 32 + lane;

        // ---- load x (fp32 regs), A = sum(x^2), convert -> interleaved bf16 --
        float4 x4[16];
        {
            const float4* xp = reinterpret_cast<const float4*>(inp + (size_t)row * DIM);
            #pragma unroll
            for (int i = 0; i < 16; i++) x4[i] = xp[i];
        }
        float a0s = 0.f, a1s = 0.f;
        #pragma unroll
        for (int i = 0; i < 16; i++) {
            a0s = fmaf(x4[i].x, x4[i].x, a0s);
            a1s = fmaf(x4[i].y, x4[i].y, a1s);
            a0s = fmaf(x4[i].z, x4[i].z, a0s);
            a1s = fmaf(x4[i].w, x4[i].w, a1s);
        }
        const float A = a0s + a1s;

        {
            unsigned w[32];
            #pragma unroll
            for (int i = 0; i < 16; i++) {
                w[2 * i]     = pack_bf2(x4[i].x, x4[i].y);
                w[2 * i + 1] = pack_bf2(x4[i].z, x4[i].w);
            }
            #pragma unroll
            for (int p = 0; p < 32; p++)
                xw[lane * 36 + p] = w[frag_remap(p)];
        }
        wcn[lane] = 0;
        __syncwarp();

        // ---- hoist A-fragments: 32 regs, conflict-free LDS.64 ---------------
        uint2 afr[2][4][2];
        #pragma unroll
        for (int mt = 0; mt < 2; mt++)
            #pragma unroll
            for (int ks = 0; ks < 4; ks++)
                #pragma unroll
                for (int h = 0; h < 2; h++)
                    afr[mt][ks][h] = *reinterpret_cast<const uint2*>(
                        &xw[(mt * 16 + g + 8 * h) * 36 + ks * 8 + 2 * tg]);

        // ---- pass 1: MMA + in-register per-row running max ------------------
        float m[4] = {-3.402823466e+38f, -3.402823466e+38f,
                      -3.402823466e+38f, -3.402823466e+38f};
        #pragma unroll 1
        for (int ch = 0; ch < 16; ch++) {
            float acc[2][4][4];
            #pragma unroll
            for (int mt = 0; mt < 2; mt++)
                #pragma unroll
                for (int nt = 0; nt < 4; nt++)
                    #pragma unroll
                    for (int e = 0; e < 4; e++) acc[mt][nt][e] = 0.f;
            #pragma unroll
            for (int ks = 0; ks < 4; ks++)
                #pragma unroll
                for (int nt = 0; nt < 4; nt++) {
                    int col = ch * 32 + nt * 8 + g;
                    uint2 bv = *reinterpret_cast<const uint2*>(
                        &codes[col * 36 + ks * 8 + 2 * tg]);
                    mma_bf16(acc[0][nt], afr[0][ks][0].x, afr[0][ks][1].x,
                             afr[0][ks][0].y, afr[0][ks][1].y, bv.x, bv.y);
                    mma_bf16(acc[1][nt], afr[1][ks][0].x, afr[1][ks][1].x,
                             afr[1][ks][0].y, afr[1][ks][1].y, bv.x, bv.y);
                }
            #pragma unroll
            for (int mt = 0; mt < 2; mt++)
                #pragma unroll
                for (int nt = 0; nt < 4; nt++) {
                    m[2*mt]   = fmaxf(m[2*mt],   fmaxf(acc[mt][nt][0], acc[mt][nt][1]));
                    m[2*mt+1] = fmaxf(m[2*mt+1], fmaxf(acc[mt][nt][2], acc[mt][nt][3]));
                }
        }
        // quad reduce (lanes 4g..4g+3 share rows g,g+8,g+16,g+24)
        #pragma unroll
        for (int s = 0; s < 4; s++) {
            m[s] = fmaxf(m[s], __shfl_xor_sync(0xFFFFFFFFu, m[s], 1));
            m[s] = fmaxf(m[s], __shfl_xor_sync(0xFFFFFFFFu, m[s], 2));
        }
        float thr[4];
        #pragma unroll
        for (int s = 0; s < 4; s++) thr[s] = m[s] - DELTA;

        // ---- pass 2: recompute MMA, detect candidates >= thr ----------------
        #pragma unroll 1
        for (int ch = 0; ch < 16; ch++) {
            float acc[2][4][4];
            #pragma unroll
            for (int mt = 0; mt < 2; mt++)
                #pragma unroll
                for (int nt = 0; nt < 4; nt++)
                    #pragma unroll
                    for (int e = 0; e < 4; e++) acc[mt][nt][e] = 0.f;
            #pragma unroll
            for (int ks = 0; ks < 4; ks++)
                #pragma unroll
                for (int nt = 0; nt < 4; nt++) {
                    int col = ch * 32 + nt * 8 + g;
                    uint2 bv = *reinterpret_cast<const uint2*>(
                        &codes[col * 36 + ks * 8 + 2 * tg]);
                    mma_bf16(acc[0][nt], afr[0][ks][0].x, afr[0][ks][1].x,
                             afr[0][ks][0].y, afr[0][ks][1].y, bv.x, bv.y);
                    mma_bf16(acc[1][nt], afr[1][ks][0].x, afr[1][ks][1].x,
                             afr[1][ks][0].y, afr[1][ks][1].y, bv.x, bv.y);
                }
            #pragma unroll
            for (int mt = 0; mt < 2; mt++)
                #pragma unroll
                for (int nt = 0; nt < 4; nt++) {
                    float h01 = fmaxf(acc[mt][nt][0], acc[mt][nt][1]);
                    float h23 = fmaxf(acc[mt][nt][2], acc[mt][nt][3]);
                    if (h01 >= thr[2*mt] || h23 >= thr[2*mt+1]) {   // rare
                        #pragma unroll
                        for (int e = 0; e < 4; e++) {
                            if (acc[mt][nt][e] >= thr[2*mt + (e >> 1)]) {
                                int r = mt * 16 + g + 8 * (e >> 1);
                                int k = ch * 32 + nt * 8 + 2 * tg + (e & 1);
                                int p = atomicAdd(&wcn[r], 1);
                                if (p < SLOTS) wls[r * SLOTS + p] = k;
                            }
                        }
                    }
                }
        }
        __syncwarp();

        // ---- exact fp32 recheck (JAX-replicating, tie -> lower k) -----------
        float bestd = 3.402823466e+38f;
        int   bik   = 0x7FFFFFFF;
        auto recheck = [&](int k) {
            const float4* ep = reinterpret_cast<const float4*>(emb + (size_t)k * DIM);
            float c0 = 0.f, c1 = 0.f;
            #pragma unroll
            for (int i = 0; i < 16; i++) {
                float4 ev = ep[i];
                c0 = fmaf(x4[i].x, ev.x, c0);
                c1 = fmaf(x4[i].y, ev.y, c1);
                c0 = fmaf(x4[i].z, ev.z, c0);
                c1 = fmaf(x4[i].w, ev.w, c1);
            }
            float c  = c0 + c1;
            float t  = A + sb[k];          // fl(A + b_k)
            float dd = t - 2.0f * c;       // fl(t - 2c)
            if (dd < bestd || (dd == bestd && k < bik)) { bestd = dd; bik = k; }
        };
        {
            int c = wcn[lane];
            if (c <= SLOTS) {
                for (int i = 0; i < c; i++) recheck(wls[lane * SLOTS + i]);
            } else {
                for (int k = 0; k < KC; k++) recheck(k);  // safety net
            }
        }

        // ---- epilogue: index, hist, quantized_st, SSE -----------------------
        out[2 + NQ + row] = (float)bik;
        atomicAdd(&g_hist[bik], 1);

        float* q = out + 1 + (size_t)row * DIM;   // base == 1 mod 4 floats
        const float4* ep = reinterpret_cast<const float4*>(emb + (size_t)bik * DIM);
        float qs[DIM];
        float sse = 0.f;
        #pragma unroll
        for (int i = 0; i < 16; i++) {
            float4 ev = ep[i];
            float d0 = ev.x - x4[i].x, d1 = ev.y - x4[i].y;
            float d2 = ev.z - x4[i].z, d3 = ev.w - x4[i].w;
            qs[4*i]   = x4[i].x + d0;             // fl(x + fl(q-x))
            qs[4*i+1] = x4[i].y + d1;
            qs[4*i+2] = x4[i].z + d2;
            qs[4*i+3] = x4[i].w + d3;
            sse += d0*d0 + d1*d1 + d2*d2 + d3*d3;
        }
        q[0] = qs[0]; q[1] = qs[1]; q[2] = qs[2];
        float4* q4 = reinterpret_cast<float4*>(q + 3);
        #pragma unroll
        for (int i = 0; i < 15; i++)
            q4[i] = make_float4(qs[3+4*i], qs[4+4*i], qs[5+4*i], qs[6+4*i]);
        q[63] = qs[63];

        float wsum = sse;
        #pragma unroll
        for (int off = 16; off > 0; off >>= 1)
            wsum += __shfl_xor_sync(0xFFFFFFFFu, wsum, off);
        if (lane == 0) atomicAdd(&g_sse, (double)wsum);

        __syncwarp();   // xw reads done before next tile overwrites
    }

    // ---- last CTA finalizes loss & perplexity -------------------------------
    __threadfence();
    __syncthreads();
    __shared__ unsigned s_last;
    if (tid == 0)
        s_last = (atomicAdd(&g_done, 1u) == GRID - 1u) ? 1u : 0u;
    __syncthreads();
    if (s_last) {
        __threadfence();
        __shared__ float red[THREADS];
        float acc = 0.f;
        for (int b = tid; b < KC; b += THREADS) {
            float pb = (float)g_hist[b] * (1.0f / (float)NROWS);
            acc += pb * logf(pb + 1e-10f);
        }
        red[tid] = acc;
        __syncthreads();
        for (int off = THREADS / 2; off > 0; off >>= 1) {
            if (tid < off) red[tid] += red[tid + off];
            __syncthreads();
        }
        if (tid == 0) {
            out[0]      = (float)(1.25 * (g_sse * (1.0 / (double)NQ)));
            out[1 + NQ] = expf(-red[0]);
        }
    }
}

extern "C" void kernel_launch(void* const* d_in, const int* in_sizes, int n_in,
                              void* d_out, int out_size)
{
    const float* inp = (const float*)d_in[0];
    const float* emb = (const float*)d_in[1];
    if (n_in >= 2 && in_sizes[0] == KC * DIM) {
        const float* t = inp; inp = emb; emb = t;
    }
    float* out = (float*)d_out;

    cudaFuncSetAttribute(vq_mma_kernel,
                         cudaFuncAttributeMaxDynamicSharedMemorySize, SMEM_TOTAL);

    prep_kernel<<<4, 128>>>(emb);
    vq_mma_kernel<<<GRID, THREADS, SMEM_TOTAL>>>(inp, emb, out);
}

// round 8
// speedup vs baseline: 2.6172x; 2.6172x over previous
#include <cuda_runtime.h>
#include <math.h>

// Problem constants
#define NROWS   65536
#define DIM     64
#define KC      512
#define NQ      (NROWS*DIM)
#define THREADS 512                     // 16 warps -> 1 CTA/SM, occ 25%
#define GRID    (NROWS/THREADS)         // 128
#define STRIDE4 17                      // float4 stride per code row (68 floats)
#define STRIDEF (STRIDE4*4)
#define SMEM_FLOATS (KC*STRIDEF + KC)   // 141,312 B

// Output layout (flattened tuple, f32):
//   [0] loss | [1..NQ] quantized_st (base out+1, 4B-aligned only)
//   [1+NQ] perplexity | [2+NQ..] indices (as float)

__device__ double       g_sse;
__device__ int          g_hist[KC];
__device__ unsigned int g_done;

// ---- packed f32x2 helpers (PTX-only; ptxas never auto-fuses) -----------------
__device__ __forceinline__ void upk2(unsigned long long v, float& lo, float& hi) {
    asm("mov.b64 {%0, %1}, %2;" : "=f"(lo), "=f"(hi) : "l"(v));
}
__device__ __forceinline__ unsigned long long fma2(unsigned long long a,
                                                   unsigned long long b,
                                                   unsigned long long c) {
    unsigned long long d;
    asm("fma.rn.f32x2 %0, %1, %2, %3;" : "=l"(d) : "l"(a), "l"(b), "l"(c));
    return d;
}
__device__ __forceinline__ unsigned long long add2(unsigned long long a,
                                                   unsigned long long b) {
    unsigned long long d;
    asm("add.rn.f32x2 %0, %1, %2;" : "=l"(d) : "l"(a), "l"(b));
    return d;
}

__global__ void init_kernel() {
    int t = blockIdx.x * blockDim.x + threadIdx.x;
    if (t < KC) g_hist[t] = 0;
    if (t == 0) { g_sse = 0.0; g_done = 0u; }
}

// -----------------------------------------------------------------------------
// Fused kernel: 1 row/thread packed-f32x2 argmin + gather/ST + SSE + hist;
// last block computes loss & perplexity.
//
// Numerics replicate JAX where it decides the result:
//   d_k = fl( fl(A + b_k) - 2*c_k ),  first-index tie-break (strict <, k asc).
// Dot-product reduction-order noise (~1e-9) is far below the ULP(64)=7.6e-6
// grid the distances are rounded onto (validated R2/R4: zero index flips).
// -----------------------------------------------------------------------------
__global__ void __launch_bounds__(THREADS, 1)
vq_fused_kernel(const float* __restrict__ inp,
                const float* __restrict__ emb,
                float* __restrict__ out)
{
    extern __shared__ float smem[];
    float* sE = smem;                 // KC rows, stride 68 floats
    float* sB = smem + KC * STRIDEF;  // KC squared norms

    // Load embedding into padded smem
    for (int i = threadIdx.x; i < KC * DIM / 4; i += THREADS) {
        int k = i >> 4, j = i & 15;
        reinterpret_cast<float4*>(sE)[k * STRIDE4 + j] =
            reinterpret_cast<const float4*>(emb)[i];
    }
    __syncthreads();

    // Per-code squared norms
    for (int k = threadIdx.x; k < KC; k += THREADS) {
        const float* e = sE + k * STRIDEF;
        float b0 = 0.f, b1 = 0.f;
        #pragma unroll
        for (int i = 0; i < DIM; i += 2) {
            b0 = fmaf(e[i],     e[i],     b0);
            b1 = fmaf(e[i + 1], e[i + 1], b1);
        }
        sB[k] = b0 + b1;
    }
    __syncthreads();

    const int row = blockIdx.x * THREADS + threadIdx.x;

    // x row: 64 floats loaded directly as 32 packed f32x2 (memory layout is
    // already [lo,hi] pairs); packed A accumulation, 4 chains.
    unsigned long long x2[32];
    float A;
    {
        const ulonglong2* xin =
            reinterpret_cast<const ulonglong2*>(inp + (size_t)row * DIM);
        unsigned long long a0 = 0ull, a1 = 0ull, a2 = 0ull, a3 = 0ull;
        #pragma unroll
        for (int i = 0; i < 16; i++) {
            ulonglong2 v = xin[i];
            x2[2 * i]     = v.x;
            x2[2 * i + 1] = v.y;
            if (i & 1) { a2 = fma2(v.x, v.x, a2); a3 = fma2(v.y, v.y, a3); }
            else       { a0 = fma2(v.x, v.x, a0); a1 = fma2(v.y, v.y, a1); }
        }
        unsigned long long s0 = add2(a0, a2), s1 = add2(a1, a3);
        float p, q, r, s;
        upk2(s0, p, q); upk2(s1, r, s);
        A = (p + r) + (q + s);
    }

    float best = 3.402823466e+38f;
    int   bi   = 0;

    #pragma unroll 2
    for (int k = 0; k < KC; k++) {
        const ulonglong2* e2 =
            reinterpret_cast<const ulonglong2*>(sE + k * STRIDEF);
        unsigned long long a0 = 0ull, a1 = 0ull, a2 = 0ull, a3 = 0ull;
        #pragma unroll
        for (int j = 0; j < 16; j++) {
            ulonglong2 ev = e2[j];        // LDS.128, broadcast across lanes
            if (j & 1) {
                a2 = fma2(x2[2 * j],     ev.x, a2);
                a3 = fma2(x2[2 * j + 1], ev.y, a3);
            } else {
                a0 = fma2(x2[2 * j],     ev.x, a0);
                a1 = fma2(x2[2 * j + 1], ev.y, a1);
            }
        }
        unsigned long long s0 = add2(a0, a2), s1 = add2(a1, a3);
        float p, q, r, s;
        upk2(s0, p, q); upk2(s1, r, s);
        float c  = (p + r) + (q + s);
        float t  = A + sB[k];            // fl(A + b_k)
        float dd = t - 2.0f * c;         // fl(t - 2c); contraction exact-equal
        if (dd < best) { best = dd; bi = k; }
    }

    // ---- fused epilogue: index, hist, quantized_st, SSE ----------------------
    out[2 + NQ + row] = (float)bi;
    atomicAdd(&g_hist[bi], 1);

    // quantized_st = fl(x + fl(q-x)); dest base == 4 (mod 16) bytes:
    // cols 0..2,63 scalar; cols 3..62 as 15 aligned float4 stores.
    float* q = out + 1 + (size_t)row * DIM;
    {
        const float4* eb = reinterpret_cast<const float4*>(sE + bi * STRIDEF);
        float qs[DIM];
        float sse = 0.f;
        #pragma unroll
        for (int j = 0; j < 16; j++) {
            float4 ev = eb[j];            // padded stride -> spread conflicts
            float xl0, xh0, xl1, xh1;
            upk2(x2[2 * j],     xl0, xh0);
            upk2(x2[2 * j + 1], xl1, xh1);
            float d0 = ev.x - xl0, d1 = ev.y - xh0;
            float d2 = ev.z - xl1, d3 = ev.w - xh1;
            qs[4 * j + 0] = xl0 + d0;
            qs[4 * j + 1] = xh0 + d1;
            qs[4 * j + 2] = xl1 + d2;
            qs[4 * j + 3] = xh1 + d3;
            sse += d0 * d0 + d1 * d1 + d2 * d2 + d3 * d3;
        }
        q[0] = qs[0]; q[1] = qs[1]; q[2] = qs[2];
        float4* q4 = reinterpret_cast<float4*>(q + 3);
        #pragma unroll
        for (int i = 0; i < 15; i++)
            q4[i] = make_float4(qs[3 + 4 * i], qs[4 + 4 * i],
                                qs[5 + 4 * i], qs[6 + 4 * i]);
        q[63] = qs[63];

        #pragma unroll
        for (int off = 16; off > 0; off >>= 1)
            sse += __shfl_xor_sync(0xFFFFFFFFu, sse, off);
        if ((threadIdx.x & 31) == 0)
            atomicAdd(&g_sse, (double)sse);
    }

    // ---- last block finalizes loss & perplexity ------------------------------
    __threadfence();
    __syncthreads();
    __shared__ unsigned int s_last;
    if (threadIdx.x == 0)
        s_last = (atomicAdd(&g_done, 1u) == gridDim.x - 1u) ? 1u : 0u;
    __syncthreads();
    if (s_last) {
        __threadfence();
        __shared__ float red[THREADS];
        float acc = 0.f;
        for (int b = threadIdx.x; b < KC; b += THREADS) {
            float pb = (float)g_hist[b] * (1.0f / (float)NROWS);
            acc += pb * logf(pb + 1e-10f);
        }
        red[threadIdx.x] = acc;
        __syncthreads();
        for (int off = THREADS / 2; off > 0; off >>= 1) {
            if (threadIdx.x < off) red[threadIdx.x] += red[threadIdx.x + off];
            __syncthreads();
        }
        if (threadIdx.x == 0) {
            out[0]      = (float)(1.25 * (g_sse * (1.0 / (double)NQ)));
            out[1 + NQ] = expf(-red[0]);
        }
    }
}

extern "C" void kernel_launch(void* const* d_in, const int* in_sizes, int n_in,
                              void* d_out, int out_size)
{
    const float* inp = (const float*)d_in[0];
    const float* emb = (const float*)d_in[1];
    if (n_in >= 2 && in_sizes[0] == KC * DIM) {
        const float* t = inp; inp = emb; emb = t;
    }
    float* out = (float*)d_out;

    const int smem_bytes = SMEM_FLOATS * sizeof(float);  // 141,312 B
    cudaFuncSetAttribute(vq_fused_kernel,
                         cudaFuncAttributeMaxDynamicSharedMemorySize,
                         smem_bytes);

    init_kernel<<<1, 512>>>();
    vq_fused_kernel<<<GRID, THREADS, smem_bytes>>>(inp, emb, out);
}

// round 9
// speedup vs baseline: 2.9199x; 1.1157x over previous
#include <cuda_runtime.h>
#include <math.h>

#define NROWS   65536
#define DIM     64
#define KC      512
#define NQ      (NROWS*DIM)
#define THREADS 512
#define MTILE   64
#define NTILES  (NROWS/MTILE)    // 1024
#define GRID    148
#define XTS     66               // padded X^T row stride (floats, even!)

// smem byte offsets
#define SMO_ET   0                        // E^T: 64 x 512 f32 = 131072 B
#define SMO_XT   131072                   // X^T: 64 x 66 f32  = 16896 B
#define SMO_SB   (SMO_XT + 16896)         // 512 f32 code norms
#define SMO_SA   (SMO_SB + 2048)          // 64 f32 row norms
#define SMO_KEYS (SMO_SA + 256)           // 64 u64 argmin keys
#define SMEM_TOTAL (SMO_KEYS + 512)       // 150784 B

// Output: [0] loss | [1..NQ] quantized_st (base out+1, 4B-aligned) |
//         [1+NQ] perplexity | [2+NQ..] indices (as float)

typedef unsigned long long ull;

__device__ float  g_ET[DIM*KC];     // E^T [d][k]
__device__ float  g_sb[KC];
__device__ int    g_hist[KC];
__device__ double g_sse;
__device__ unsigned g_done;

__device__ __forceinline__ ull splat2(float v) {
    ull r; asm("mov.b64 %0, {%1, %1};" : "=l"(r) : "f"(v)); return r;
}
__device__ __forceinline__ void upk2(ull v, float& lo, float& hi) {
    asm("mov.b64 {%0, %1}, %2;" : "=f"(lo), "=f"(hi) : "l"(v));
}
__device__ __forceinline__ ull fma2(ull a, ull b, ull c) {
    ull d; asm("fma.rn.f32x2 %0, %1, %2, %3;" : "=l"(d) : "l"(a), "l"(b), "l"(c));
    return d;
}
// order-preserving float -> u32 (total order), for (dd, k) min keys
__device__ __forceinline__ unsigned ord32(float f) {
    unsigned u = __float_as_uint(f);
    return (u & 0x80000000u) ? ~u : (u | 0x80000000u);
}

// ---- prep: E^T image + exact code norms + zero globals ----------------------
__global__ void prep_kernel(const float* __restrict__ emb) {
    int k = blockIdx.x * blockDim.x + threadIdx.x;
    if (k >= KC) return;
    if (k == 0) { g_sse = 0.0; g_done = 0u; }
    g_hist[k] = 0;

    const float* e = emb + (size_t)k * DIM;
    float b0 = 0.f, b1 = 0.f;
    #pragma unroll
    for (int i = 0; i < DIM; i += 2) {
        b0 = fmaf(e[i],     e[i],     b0);
        b1 = fmaf(e[i + 1], e[i + 1], b1);
    }
    g_sb[k] = b0 + b1;
    #pragma unroll
    for (int d = 0; d < DIM; d++)
        g_ET[d * KC + k] = e[d];
}

// -----------------------------------------------------------------------------
// Persistent GEMM-tiled VQ kernel: 64-row tiles x 512 codes, 8x8 register
// blocking with f32x2. Exact JAX-replicating argmin:
//   d_k = fl( fl(A + b_k) - 2*c_k ), first-index tie-break via (dd,k) min-key.
// -----------------------------------------------------------------------------
__global__ void __launch_bounds__(THREADS, 1)
vq_gemm_kernel(const float* __restrict__ inp,
               const float* __restrict__ emb,
               float* __restrict__ out)
{
    extern __shared__ char smc[];
    float* ET   = reinterpret_cast<float*>(smc + SMO_ET);
    float* XT   = reinterpret_cast<float*>(smc + SMO_XT);
    float* sbv  = reinterpret_cast<float*>(smc + SMO_SB);
    float* sA   = reinterpret_cast<float*>(smc + SMO_SA);
    ull*   keys = reinterpret_cast<ull*>(smc + SMO_KEYS);

    const int tid  = threadIdx.x;
    const int lane = tid & 31;
    const int rp   = tid >> 6;    // row-group 0..7 (8 rows each)
    const int cg   = tid & 63;    // code lane: codes cg + 64*j

    // one-time smem fill: E^T + code norms
    for (int i = tid; i < DIM * KC / 4; i += THREADS)
        reinterpret_cast<float4*>(ET)[i] =
            reinterpret_cast<const float4*>(g_ET)[i];
    for (int i = tid; i < KC; i += THREADS) sbv[i] = g_sb[i];

    for (int tile = blockIdx.x; tile < NTILES; tile += GRID) {
        // ---- prologue: rows 0..63 -> X^T (stride 66), row norms, key init ---
        __syncthreads();   // prior tile's reads done; (first iter: ET fill)
        if (tid < MTILE) {
            const float4* xp = reinterpret_cast<const float4*>(
                inp + (size_t)(tile * MTILE + tid) * DIM);
            float a0 = 0.f, a1 = 0.f;
            #pragma unroll
            for (int i = 0; i < 16; i++) {
                float4 v = xp[i];
                XT[(4 * i + 0) * XTS + tid] = v.x;
                XT[(4 * i + 1) * XTS + tid] = v.y;
                XT[(4 * i + 2) * XTS + tid] = v.z;
                XT[(4 * i + 3) * XTS + tid] = v.w;
                a0 = fmaf(v.x, v.x, a0);
                a1 = fmaf(v.y, v.y, a1);
                a0 = fmaf(v.z, v.z, a0);
                a1 = fmaf(v.w, v.w, a1);
            }
            sA[tid]   = a0 + a1;
            keys[tid] = ~0ull;
        }
        __syncthreads();

        // ---- mainloop: acc[i2][j] = c for rows (rp*8+2i2, +1), code cg+64j --
        ull acc[4][8];
        #pragma unroll
        for (int i2 = 0; i2 < 4; i2++)
            #pragma unroll
            for (int j = 0; j < 8; j++) acc[i2][j] = 0ull;

        const float* ETc = ET + cg;
        const float* XTr = XT + rp * 8;
        #pragma unroll 4
        for (int d = 0; d < DIM; d++) {
            ull x2[4];
            #pragma unroll
            for (int i2 = 0; i2 < 4; i2++)
                x2[i2] = *reinterpret_cast<const ull*>(XTr + d * XTS + 2 * i2);
            #pragma unroll
            for (int j = 0; j < 8; j++) {
                ull es = splat2(ETc[d * KC + 64 * j]);
                acc[0][j] = fma2(x2[0], es, acc[0][j]);
                acc[1][j] = fma2(x2[1], es, acc[1][j]);
                acc[2][j] = fma2(x2[2], es, acc[2][j]);
                acc[3][j] = fma2(x2[3], es, acc[3][j]);
            }
        }

        // ---- per-row local argmin keys over this thread's 8 codes ----------
        ull lkey[8];
        #pragma unroll
        for (int i = 0; i < 8; i++) lkey[i] = ~0ull;
        #pragma unroll
        for (int i2 = 0; i2 < 4; i2++) {
            float tA0 = sA[rp * 8 + 2 * i2];
            float tA1 = sA[rp * 8 + 2 * i2 + 1];
            #pragma unroll
            for (int j = 0; j < 8; j++) {
                int   k = cg + 64 * j;
                float b = sbv[k];
                float clo, chi;
                upk2(acc[i2][j], clo, chi);
                float t0  = tA0 + b;              // fl(A + b_k)
                float dd0 = t0 - 2.0f * clo;      // fl(t - 2c)
                ull  k0 = ((ull)ord32(dd0) << 32) | (unsigned)k;
                if (k0 < lkey[2 * i2]) lkey[2 * i2] = k0;
                float t1  = tA1 + b;
                float dd1 = t1 - 2.0f * chi;
                ull  k1 = ((ull)ord32(dd1) << 32) | (unsigned)k;
                if (k1 < lkey[2 * i2 + 1]) lkey[2 * i2 + 1] = k1;
            }
        }
        // warp min-reduce, then shared atomicMin (2 warps per row-group)
        #pragma unroll
        for (int i = 0; i < 8; i++) {
            ull v = lkey[i];
            #pragma unroll
            for (int off = 16; off > 0; off >>= 1) {
                ull o = __shfl_xor_sync(0xFFFFFFFFu, v, off);
                v = (o < v) ? o : v;
            }
            if (lane == 0) atomicMin(&keys[rp * 8 + i], v);
        }
        __syncthreads();

        // ---- winners: 64 threads finish one row each ------------------------
        if (tid < MTILE) {
            const int row = tile * MTILE + tid;
            const int bik = (int)(unsigned)(keys[tid] & 0xFFFFFFFFull);

            out[2 + NQ + row] = (float)bik;
            atomicAdd(&g_hist[bik], 1);

            const float4* xp = reinterpret_cast<const float4*>(
                inp + (size_t)row * DIM);
            const float4* ep = reinterpret_cast<const float4*>(
                emb + (size_t)bik * DIM);
            float* q = out + 1 + (size_t)row * DIM;  // base == 4 (mod 16) B

            float qs[DIM];
            float sse = 0.f;
            #pragma unroll
            for (int i = 0; i < 16; i++) {
                float4 xv = xp[i], ev = ep[i];
                float d0 = ev.x - xv.x, d1 = ev.y - xv.y;
                float d2 = ev.z - xv.z, d3 = ev.w - xv.w;
                qs[4*i]   = xv.x + d0;               // fl(x + fl(q-x))
                qs[4*i+1] = xv.y + d1;
                qs[4*i+2] = xv.z + d2;
                qs[4*i+3] = xv.w + d3;
                sse += d0*d0 + d1*d1 + d2*d2 + d3*d3;
            }
            q[0] = qs[0]; q[1] = qs[1]; q[2] = qs[2];
            float4* q4 = reinterpret_cast<float4*>(q + 3);
            #pragma unroll
            for (int i = 0; i < 15; i++)
                q4[i] = make_float4(qs[3+4*i], qs[4+4*i], qs[5+4*i], qs[6+4*i]);
            q[63] = qs[63];

            #pragma unroll
            for (int off = 16; off > 0; off >>= 1)
                sse += __shfl_xor_sync(0xFFFFFFFFu, sse, off);
            if (lane == 0) atomicAdd(&g_sse, (double)sse);
        }
    }

    // ---- last CTA finalizes loss & perplexity -------------------------------
    __threadfence();
    __syncthreads();
    __shared__ unsigned s_last;
    if (tid == 0)
        s_last = (atomicAdd(&g_done, 1u) == GRID - 1u) ? 1u : 0u;
    __syncthreads();
    if (s_last) {
        __threadfence();
        __shared__ float red[THREADS];
        float acc = 0.f;
        for (int b = tid; b < KC; b += THREADS) {
            float pb = (float)g_hist[b] * (1.0f / (float)NROWS);
            acc += pb * logf(pb + 1e-10f);
        }
        red[tid] = acc;
        __syncthreads();
        for (int off = THREADS / 2; off > 0; off >>= 1) {
            if (tid < off) red[tid] += red[tid + off];
            __syncthreads();
        }
        if (tid == 0) {
            out[0]      = (float)(1.25 * (g_sse * (1.0 / (double)NQ)));
            out[1 + NQ] = expf(-red[0]);
        }
    }
}

extern "C" void kernel_launch(void* const* d_in, const int* in_sizes, int n_in,
                              void* d_out, int out_size)
{
    const float* inp = (const float*)d_in[0];
    const float* emb = (const float*)d_in[1];
    if (n_in >= 2 && in_sizes[0] == KC * DIM) {
        const float* t = inp; inp = emb; emb = t;
    }
    float* out = (float*)d_out;

    cudaFuncSetAttribute(vq_gemm_kernel,
                         cudaFuncAttributeMaxDynamicSharedMemorySize,
                         SMEM_TOTAL);

    prep_kernel<<<4, 128>>>(emb);
    vq_gemm_kernel<<<GRID, THREADS, SMEM_TOTAL>>>(inp, emb, out);
}